// round 17
// baseline (speedup 1.0000x reference)
#include <cuda_runtime.h>
#include <cstdint>

#define T 128            // threads per block = rows per block
#define RPB 128
#define NCOLS 14
#define IN_BYTES  (RPB * NCOLS * 4)   // 14336 B per tile
#define W_BYTES   (IN_BYTES / 4)      //  3584 B per warp chunk (32 rows)

__device__ __forceinline__ uint32_t smem_u32(const void* p) {
    uint32_t a;
    asm("{ .reg .u64 t; cvta.to.shared.u64 t, %1; cvt.u32.u64 %0, t; }" : "=r"(a) : "l"(p));
    return a;
}

__global__ __launch_bounds__(T, 16)   // 16 CTAs/SM (2048 threads)
void indicator_kernel(const float* __restrict__ in, float* __restrict__ out) {
    __shared__ alignas(128) float s_in[RPB * NCOLS];   // 7168 B
    __shared__ alignas(128) float s_out[RPB * 3];      // 1536 B
    __shared__ alignas(8)  uint64_t mbar[4];           // one per warp

    const int tid = threadIdx.x;
    const int w   = tid >> 5;             // warp 0..3
    const int l   = tid & 31;             // lane
    const int bid = blockIdx.x;

    const uint32_t mb = smem_u32(&mbar[w]);

    // ---- per-warp bulk-async load: warp w's 32 rows (3584 B), own mbarrier ----
    if (l == 0) {
        asm volatile("mbarrier.init.shared.b64 [%0], 1;" :: "r"(mb) : "memory");
    }
    __syncwarp();      // init visible to this warp (only this warp touches mb)
    if (l == 0) {
        asm volatile("mbarrier.arrive.expect_tx.shared.b64 _, [%0], %1;"
                     :: "r"(mb), "n"(W_BYTES) : "memory");
        const char* src = (const char*)in + (size_t)bid * IN_BYTES + w * W_BYTES;
        const uint32_t dst = smem_u32(s_in) + w * W_BYTES;
        asm volatile(
            "cp.async.bulk.shared::cta.global.mbarrier::complete_tx::bytes [%0], [%1], %2, [%3];"
            :: "r"(dst), "l"(src), "n"(W_BYTES), "r"(mb) : "memory");
    }
    // all lanes of this warp wait on this warp's barrier only (phase 0)
    {
        uint32_t done = 0;
        while (!done) {
            asm volatile("{\n\t.reg .pred p;\n\t"
                "mbarrier.try_wait.parity.acquire.cta.shared::cta.b64 p, [%1], 0, 0x989680;\n\t"
                "selp.b32 %0, 1, 0, p;\n\t}"
                : "=r"(done) : "r"(mb) : "memory");
        }
    }

    // ---- per-row compute: one row per thread (reads only own warp's chunk) ----
    {
        const float*  r  = &s_in[tid * NCOLS];
        const float2* r2 = (const float2*)r;          // 56*t bytes -> 8B aligned
        const float2 oc  = r2[0];   // cols 0,1
        const float  lw  = r[5];
        const float  uw  = r[6];
        const float2 ms  = r2[4];   // cols 8,9
        const float2 sbv = r2[5];   // cols 10,11
        const float2 mbl = r2[6];   // cols 12,13
        const float ha_open = oc.x, ha_close = oc.y;
        const float ma = ms.x, srsi = ms.y;
        const float ssig = sbv.x, bu = sbv.y;
        const float bm = mbl.x,  bl = mbl.y;

        const bool  bullish = ha_close > ha_open;
        const bool  bearish = ha_close < ha_open;
        const float body    = fabsf(ha_close - ha_open);
        const bool  sb_ = bullish && (body > 0.5f) && (uw < 1e-6f);  // strong_bullish
        const bool  sB_ = bearish && (body > 0.5f) && (lw < 1e-6f);  // strong_bearish

        const float ha2 = sb_ ? 0.8f : 0.0f;
        const float ha0 = sB_ ? 0.8f : 0.0f;

        const float width = (bu - bl) / bm;
        const float pp    = (ha_close - bl) / (bu - bl);
        // structurally false, kept for exact fidelity (NaN behavior identical):
        const bool  sqexp = (width < 0.1f) && (width > 0.2f);
        const float sqf   = sqexp ? 0.9f : 0.0f;

        const bool pp_lo = pp < 0.2f;
        const bool pp_hi = pp > 0.8f;
        const float bb2 = (pp_lo ? 0.8f : 0.0f) + sqf;
        const float bb0 = (pp_hi ? 0.8f : 0.0f) + sqf;

        const float st2 = (srsi < 0.2f) ? 0.8f : 0.0f;
        const float st0 = (srsi > 0.8f) ? 0.8f : 0.0f;

        const bool  ma_up = ma > 0.1f;
        const bool  ma_dn = ma < -0.1f;
        const float ma2 = ma_up ? 0.7f : 0.0f;
        const float ma0 = ma_dn ? 0.7f : 0.0f;

        const bool st_dn = ssig < -0.1f;
        const bool st_up = ssig > 0.1f;

        // OR of all 3-of-4 conjunctions == majority(>=3 of 4)
        const bool long_sig  = ((int)sb_ + (int)ma_up + (int)st_dn + (int)pp_lo) >= 3;
        const bool short_sig = ((int)sB_ + (int)ma_dn + (int)st_up + (int)pp_hi) >= 3;

        const float hms2 = long_sig  ? 0.9f : 0.0f;
        const float hms0 = short_sig ? 0.9f : 0.0f;

        const float col0 = ha0 + ma0 + st0 + bb0 + 2.0f * hms0;
        const float col2 = ha2 + ma2 + st2 + bb2 + 2.0f * hms2;
        const float col1 = 1.5f;

        const float m  = fmaxf(fmaxf(col0, col2), col1);
        const float e0 = __expf(col0 - m);
        const float e1 = __expf(col1 - m);
        const float e2 = __expf(col2 - m);
        const float inv = 1.0f / (e0 + e1 + e2);

        s_out[tid * 3 + 0] = e0 * inv;
        s_out[tid * 3 + 1] = e1 * inv;
        s_out[tid * 3 + 2] = e2 * inv;
    }
    __syncwarp();                             // order s_out writes within the warp

    // ---- warp-local coalesced store: 96 contiguous floats per warp ----
    const int ob = bid * (RPB * 3) + w * 96;
    #pragma unroll
    for (int j = 0; j < 3; j++)
        out[ob + l + j * 32] = s_out[w * 96 + l + j * 32];
}

extern "C" void kernel_launch(void* const* d_in, const int* in_sizes, int n_in,
                              void* d_out, int out_size) {
    const float* in = (const float*)d_in[0];
    float* out = (float*)d_out;
    const int n = in_sizes[0] / NCOLS;       // 2,000,000 rows (divisible by 128)
    const int grid = n / RPB;                // 15625 blocks, all full
    indicator_kernel<<<grid, T>>>(in, out);
}